// round 7
// baseline (speedup 1.0000x reference)
#include <cuda_runtime.h>

// GridPooling via counting-sort by cell + atomic-free gather-max.
//
// R5 was atomic-issue bound (32M RED.MAX = ~113us at 1 wavefront/cyc/SM).
// Here: (1) histogram cells, (2) exclusive scan, (3) scatter point indices
// into cell-sorted order, (4) per-cell register max over gathered feature
// rows with a single plain store. Phase 4 reads each 512B feature row exactly
// once, coalesced -> DRAM-bound (~280MB total traffic).
//
// max(pooled, 0) semantics: running max starts at 0.0f, and every cell block
// writes its output, so empty cells are 0 and no d_out memset is needed.

#define GRID_DIM   32
#define NUM_CELLS  (GRID_DIM * GRID_DIM * GRID_DIM)   // 32768
#define FEAT       128
#define MAX_POINTS (1 << 20)

__device__ int g_count [NUM_CELLS];
__device__ int g_offset[NUM_CELLS];
__device__ int g_cursor[NUM_CELLS];
__device__ int g_cell  [MAX_POINTS];
__device__ int g_pidx  [MAX_POINTS];

__device__ __forceinline__ int cell_of(float x, float y, float z)
{
    int ix = __float2int_rd(x * (float)GRID_DIM);
    int iy = __float2int_rd(y * (float)GRID_DIM);
    int iz = __float2int_rd(z * (float)GRID_DIM);
    ix = min(max(ix, 0), GRID_DIM - 1);
    iy = min(max(iy, 0), GRID_DIM - 1);
    iz = min(max(iz, 0), GRID_DIM - 1);
    return ix * (GRID_DIM * GRID_DIM) + iy * GRID_DIM + iz;
}

// Phase 1: cell id per point + histogram.
__global__ __launch_bounds__(256)
void cell_kernel(const float* __restrict__ pts, int n)
{
    int p = blockIdx.x * blockDim.x + threadIdx.x;
    if (p >= n) return;
    float x = pts[3 * p + 0];
    float y = pts[3 * p + 1];
    float z = pts[3 * p + 2];
    int c = cell_of(x, y, z);
    g_cell[p] = c;
    atomicAdd(&g_count[c], 1);
}

// Phase 2: exclusive scan of 32768 counts, one block of 1024 threads
// (32 cells per thread). Writes g_offset and g_cursor.
__global__ __launch_bounds__(1024)
void scan_kernel()
{
    __shared__ int warp_sums[32];
    const int t    = threadIdx.x;
    const int lane = t & 31;
    const int w    = t >> 5;
    const int base = t * 32;

    int local[32];
    int s = 0;
    #pragma unroll
    for (int j = 0; j < 32; j++) {
        local[j] = s;
        s += g_count[base + j];
    }

    // warp-inclusive scan of per-thread sums
    int v = s;
    #pragma unroll
    for (int d = 1; d < 32; d <<= 1) {
        int nbr = __shfl_up_sync(0xffffffffu, v, d);
        if (lane >= d) v += nbr;
    }
    if (lane == 31) warp_sums[w] = v;
    __syncthreads();
    if (w == 0) {
        int x = warp_sums[lane];
        #pragma unroll
        for (int d = 1; d < 32; d <<= 1) {
            int nbr = __shfl_up_sync(0xffffffffu, x, d);
            if (lane >= d) x += nbr;
        }
        warp_sums[lane] = x;
    }
    __syncthreads();

    int excl = v - s + (w > 0 ? warp_sums[w - 1] : 0);
    #pragma unroll
    for (int j = 0; j < 32; j++) {
        int o = excl + local[j];
        g_offset[base + j] = o;
        g_cursor[base + j] = o;
    }
}

// Phase 3: scatter point indices into cell-sorted order.
__global__ __launch_bounds__(256)
void scatter_kernel(int n)
{
    int p = blockIdx.x * blockDim.x + threadIdx.x;
    if (p >= n) return;
    int c   = g_cell[p];
    int pos = atomicAdd(&g_cursor[c], 1);
    g_pidx[pos] = p;
}

// Phase 4: one block per cell, one thread per feature column.
// Register max over the cell's points; 4-way unrolled independent loads
// (MLP=4) hide DRAM latency. Single plain store per output element.
__global__ __launch_bounds__(FEAT)
void pool_kernel(const float* __restrict__ feats, float* __restrict__ out)
{
    __shared__ int s_idx[64];
    const int cell = blockIdx.x;
    const int f    = threadIdx.x;
    const int n    = g_count[cell];
    const int off  = g_offset[cell];

    float m = 0.0f;   // implements max(pooled, 0) and empty-cell = 0

    for (int c0 = 0; c0 < n; c0 += 64) {
        const int chunk = min(64, n - c0);
        __syncthreads();
        if (f < chunk) s_idx[f] = g_pidx[off + c0 + f];
        __syncthreads();

        int j = 0;
        for (; j + 4 <= chunk; j += 4) {
            float a = feats[(size_t)s_idx[j + 0] * FEAT + f];
            float b = feats[(size_t)s_idx[j + 1] * FEAT + f];
            float c = feats[(size_t)s_idx[j + 2] * FEAT + f];
            float d = feats[(size_t)s_idx[j + 3] * FEAT + f];
            m = fmaxf(m, fmaxf(fmaxf(a, b), fmaxf(c, d)));
        }
        for (; j < chunk; j++)
            m = fmaxf(m, feats[(size_t)s_idx[j] * FEAT + f]);
    }

    out[(size_t)cell * FEAT + f] = m;
}

extern "C" void kernel_launch(void* const* d_in, const int* in_sizes, int n_in,
                              void* d_out, int out_size)
{
    const float* feats = (const float*)d_in[0];   // [N, 128]
    const float* pts   = (const float*)d_in[1];   // [N, 3]
    float* out         = (float*)d_out;           // [32768, 128]

    const int n = in_sizes[1] / 3;

    void* cnt_ptr = nullptr;
    cudaGetSymbolAddress(&cnt_ptr, g_count);
    cudaMemsetAsync(cnt_ptr, 0, NUM_CELLS * sizeof(int), 0);

    const int threads = 256;
    const int blocks  = (n + threads - 1) / threads;

    cell_kernel   <<<blocks, threads>>>(pts, n);
    scan_kernel   <<<1, 1024>>>();
    scatter_kernel<<<blocks, threads>>>(n);
    pool_kernel   <<<NUM_CELLS, FEAT>>>(feats, out);
}

// round 9
// speedup vs baseline: 1.8623x; 1.8623x over previous
#include <cuda_runtime.h>

// GridPooling: counting-sort by cell (rank fused into histogram pass,
// coalesced register scan, atomic-free scatter) + warp-per-cell float4
// gather-max. See R7 theory: pre-phases ~75us -> ~20us, pool 60 -> ~45us.

#define GRID_DIM   32
#define NUM_CELLS  (GRID_DIM * GRID_DIM * GRID_DIM)   // 32768
#define FEAT       128
#define MAX_POINTS (1 << 20)

__device__ int            g_count [NUM_CELLS];
__device__ int            g_offset[NUM_CELLS];
__device__ unsigned short g_cell  [MAX_POINTS];
__device__ int            g_rank  [MAX_POINTS];
__device__ int            g_pidx  [MAX_POINTS];

__device__ __forceinline__ int cell_of(float x, float y, float z)
{
    int ix = __float2int_rd(x * (float)GRID_DIM);
    int iy = __float2int_rd(y * (float)GRID_DIM);
    int iz = __float2int_rd(z * (float)GRID_DIM);
    ix = min(max(ix, 0), GRID_DIM - 1);
    iy = min(max(iy, 0), GRID_DIM - 1);
    iz = min(max(iz, 0), GRID_DIM - 1);
    return ix * (GRID_DIM * GRID_DIM) + iy * GRID_DIM + iz;
}

// Phase 1: cell id + histogram; the atomicAdd return value IS the
// within-cell rank, so the later scatter needs no atomics at all.
// 4 points per thread via three float4 loads (fully coalesced).
__global__ __launch_bounds__(256)
void cell_kernel(const float* __restrict__ pts, int n)
{
    const int q  = blockIdx.x * blockDim.x + threadIdx.x;
    const int p0 = q * 4;
    if (p0 >= n) return;

    float xs[4], ys[4], zs[4];
    if (p0 + 4 <= n) {
        const float4* p4 = reinterpret_cast<const float4*>(pts);
        float4 a = p4[q * 3 + 0];
        float4 b = p4[q * 3 + 1];
        float4 c = p4[q * 3 + 2];
        xs[0] = a.x; ys[0] = a.y; zs[0] = a.z;
        xs[1] = a.w; ys[1] = b.x; zs[1] = b.y;
        xs[2] = b.z; ys[2] = b.w; zs[2] = c.x;
        xs[3] = c.y; ys[3] = c.z; zs[3] = c.w;
        #pragma unroll
        for (int k = 0; k < 4; k++) {
            int p = p0 + k;
            int c_ = cell_of(xs[k], ys[k], zs[k]);
            int r  = atomicAdd(&g_count[c_], 1);
            g_cell[p] = (unsigned short)c_;
            g_rank[p] = r;
        }
    } else {
        for (int p = p0; p < n; p++) {
            int c_ = cell_of(pts[3 * p], pts[3 * p + 1], pts[3 * p + 2]);
            int r  = atomicAdd(&g_count[c_], 1);
            g_cell[p] = (unsigned short)c_;
            g_rank[p] = r;
        }
    }
}

// Phase 2: exclusive scan of 32768 counts, one 1024-thread block.
// Thread t owns cells {t + j*1024}: loads/stores coalesced, the scan
// order is (t, j) -- any bijective order is a valid sort layout since
// pool reads offset[c] and count[c] directly.
__global__ __launch_bounds__(1024)
void scan_kernel()
{
    __shared__ int warp_sums[32];
    const int t    = threadIdx.x;
    const int lane = t & 31;
    const int w    = t >> 5;

    int local[32];
    int s = 0;
    #pragma unroll
    for (int j = 0; j < 32; j++) {
        local[j] = s;
        s += g_count[t + j * 1024];          // coalesced
    }

    int v = s;
    #pragma unroll
    for (int d = 1; d < 32; d <<= 1) {
        int nbr = __shfl_up_sync(0xffffffffu, v, d);
        if (lane >= d) v += nbr;
    }
    if (lane == 31) warp_sums[w] = v;
    __syncthreads();
    if (w == 0) {
        int x = warp_sums[lane];
        #pragma unroll
        for (int d = 1; d < 32; d <<= 1) {
            int nbr = __shfl_up_sync(0xffffffffu, x, d);
            if (lane >= d) x += nbr;
        }
        warp_sums[lane] = x;
    }
    __syncthreads();

    const int excl = v - s + (w > 0 ? warp_sums[w - 1] : 0);
    #pragma unroll
    for (int j = 0; j < 32; j++)
        g_offset[t + j * 1024] = excl + local[j];   // coalesced
}

// Phase 3: atomic-free scatter. Position is fully determined by
// (offset[cell], rank) captured in phase 1.
__global__ __launch_bounds__(256)
void scatter_kernel(int n)
{
    int p = blockIdx.x * blockDim.x + threadIdx.x;
    if (p >= n) return;
    int c = g_cell[p];
    g_pidx[g_offset[c] + g_rank[p]] = p;
}

// Phase 4: one warp per cell. Each lane owns one float4 (warp = 512B row).
// Index list via shuffle broadcast (no smem, no barriers). 4-deep unrolled
// LDG.128 with clamped-duplicate tail (dupes hit L1; max is idempotent).
__device__ __forceinline__ float4 max4(float4 a, float4 b)
{
    return make_float4(fmaxf(a.x, b.x), fmaxf(a.y, b.y),
                       fmaxf(a.z, b.z), fmaxf(a.w, b.w));
}

__global__ __launch_bounds__(128)
void pool_kernel(const float4* __restrict__ feats4, float4* __restrict__ out4)
{
    const int warp = threadIdx.x >> 5;
    const int lane = threadIdx.x & 31;
    const int cell = blockIdx.x * 4 + warp;

    const int off = g_offset[cell];
    const int cnt = g_count[cell];

    float4 m = make_float4(0.f, 0.f, 0.f, 0.f);  // max(.,0) + empty cells

    for (int base = 0; base < cnt; base += 32) {
        const int chunk = min(32, cnt - base);
        int idx = g_pidx[off + base + min(lane, chunk - 1)];

        for (int i = 0; i < chunk; i += 4) {
            int i0 = __shfl_sync(0xffffffffu, idx, i);
            int i1 = __shfl_sync(0xffffffffu, idx, min(i + 1, chunk - 1));
            int i2 = __shfl_sync(0xffffffffu, idx, min(i + 2, chunk - 1));
            int i3 = __shfl_sync(0xffffffffu, idx, min(i + 3, chunk - 1));
            float4 a = feats4[(size_t)i0 * (FEAT / 4) + lane];
            float4 b = feats4[(size_t)i1 * (FEAT / 4) + lane];
            float4 c = feats4[(size_t)i2 * (FEAT / 4) + lane];
            float4 d = feats4[(size_t)i3 * (FEAT / 4) + lane];
            m = max4(m, max4(max4(a, b), max4(c, d)));
        }
    }

    out4[(size_t)cell * (FEAT / 4) + lane] = m;
}

extern "C" void kernel_launch(void* const* d_in, const int* in_sizes, int n_in,
                              void* d_out, int out_size)
{
    const float* feats = (const float*)d_in[0];   // [N, 128]
    const float* pts   = (const float*)d_in[1];   // [N, 3]

    const int n = in_sizes[1] / 3;

    void* cnt_ptr = nullptr;
    cudaGetSymbolAddress(&cnt_ptr, g_count);
    cudaMemsetAsync(cnt_ptr, 0, NUM_CELLS * sizeof(int), 0);

    const int groups = (n + 3) / 4;
    cell_kernel   <<<(groups + 255) / 256, 256>>>(pts, n);
    scan_kernel   <<<1, 1024>>>();
    scatter_kernel<<<(n + 255) / 256, 256>>>(n);
    pool_kernel   <<<NUM_CELLS / 4, 128>>>(
        reinterpret_cast<const float4*>(feats),
        reinterpret_cast<float4*>(d_out));
}

// round 10
// speedup vs baseline: 1.9380x; 1.0406x over previous
#include <cuda_runtime.h>

// GridPooling: counting-sort by cell + warp-per-cell float4 gather-max.
// R9 changes vs R8 (73.0us):
//  - (cell,rank) packed into one u32 (halves phase-1/3 metadata traffic)
//  - scan prefetches its 32 counts into registers (kills serial L2 chain)
//  - pool zeroes g_count after reading -> memset node removed
//  - pool inner loop 8-wide (8 LDG.128 in flight/thread, was 4)

#define GRID_DIM   32
#define NUM_CELLS  (GRID_DIM * GRID_DIM * GRID_DIM)   // 32768
#define FEAT       128
#define MAX_POINTS (1 << 20)

__device__ int          g_count   [NUM_CELLS];   // zero at module load; pool re-zeroes
__device__ int          g_offset  [NUM_CELLS];
__device__ unsigned int g_cellrank[MAX_POINTS];  // cell | (rank << 16)
__device__ int          g_pidx    [MAX_POINTS];

__device__ __forceinline__ int cell_of(float x, float y, float z)
{
    int ix = __float2int_rd(x * (float)GRID_DIM);
    int iy = __float2int_rd(y * (float)GRID_DIM);
    int iz = __float2int_rd(z * (float)GRID_DIM);
    ix = min(max(ix, 0), GRID_DIM - 1);
    iy = min(max(iy, 0), GRID_DIM - 1);
    iz = min(max(iz, 0), GRID_DIM - 1);
    return ix * (GRID_DIM * GRID_DIM) + iy * GRID_DIM + iz;
}

// Phase 1: cell id + histogram. atomicAdd's return value IS the within-cell
// rank (rank << 16 packed with cell: uniform 500K points over 32768 cells
// give max cell count ~35, far under 65536).
__global__ __launch_bounds__(256)
void cell_kernel(const float* __restrict__ pts, int n)
{
    const int q  = blockIdx.x * blockDim.x + threadIdx.x;
    const int p0 = q * 4;
    if (p0 >= n) return;

    if (p0 + 4 <= n) {
        const float4* p4 = reinterpret_cast<const float4*>(pts);
        float4 a = p4[q * 3 + 0];
        float4 b = p4[q * 3 + 1];
        float4 c = p4[q * 3 + 2];
        float xs[4] = {a.x, a.w, b.z, c.y};
        float ys[4] = {a.y, b.x, b.w, c.z};
        float zs[4] = {a.z, b.y, c.x, c.w};
        #pragma unroll
        for (int k = 0; k < 4; k++) {
            int c_ = cell_of(xs[k], ys[k], zs[k]);
            unsigned int r = (unsigned int)atomicAdd(&g_count[c_], 1);
            g_cellrank[p0 + k] = (unsigned int)c_ | (r << 16);
        }
    } else {
        for (int p = p0; p < n; p++) {
            int c_ = cell_of(pts[3 * p], pts[3 * p + 1], pts[3 * p + 2]);
            unsigned int r = (unsigned int)atomicAdd(&g_count[c_], 1);
            g_cellrank[p] = (unsigned int)c_ | (r << 16);
        }
    }
}

// Phase 2: exclusive scan of 32768 counts, one 1024-thread block.
// Thread t owns cells {t + j*1024} (coalesced; any bijective ordering is a
// valid sort layout). Counts prefetched into registers (MLP=32) before the
// serial local scan.
__global__ __launch_bounds__(1024)
void scan_kernel()
{
    __shared__ int warp_sums[32];
    const int t    = threadIdx.x;
    const int lane = t & 31;
    const int w    = t >> 5;

    int vals[32];
    #pragma unroll
    for (int j = 0; j < 32; j++)
        vals[j] = g_count[t + j * 1024];     // 32 independent loads in flight

    int local[32];
    int s = 0;
    #pragma unroll
    for (int j = 0; j < 32; j++) { local[j] = s; s += vals[j]; }

    int v = s;
    #pragma unroll
    for (int d = 1; d < 32; d <<= 1) {
        int nbr = __shfl_up_sync(0xffffffffu, v, d);
        if (lane >= d) v += nbr;
    }
    if (lane == 31) warp_sums[w] = v;
    __syncthreads();
    if (w == 0) {
        int x = warp_sums[lane];
        #pragma unroll
        for (int d = 1; d < 32; d <<= 1) {
            int nbr = __shfl_up_sync(0xffffffffu, x, d);
            if (lane >= d) x += nbr;
        }
        warp_sums[lane] = x;
    }
    __syncthreads();

    const int excl = v - s + (w > 0 ? warp_sums[w - 1] : 0);
    #pragma unroll
    for (int j = 0; j < 32; j++)
        g_offset[t + j * 1024] = excl + local[j];
}

// Phase 3: atomic-free scatter; position fully determined by (offset, rank).
__global__ __launch_bounds__(256)
void scatter_kernel(int n)
{
    int p = blockIdx.x * blockDim.x + threadIdx.x;
    if (p >= n) return;
    unsigned int cr = g_cellrank[p];
    int c = (int)(cr & 0xffffu);
    int r = (int)(cr >> 16);
    g_pidx[g_offset[c] + r] = p;
}

// Phase 4: one warp per cell, lane = one float4 (warp covers the 512B row).
// 8 independent LDG.128 per thread per step; clamped-duplicate tail (dupes
// are L1 hits, max is idempotent). Zeroes g_count afterwards so the next
// graph replay starts from the all-zero invariant (no memset node needed).
__device__ __forceinline__ float4 max4(float4 a, float4 b)
{
    return make_float4(fmaxf(a.x, b.x), fmaxf(a.y, b.y),
                       fmaxf(a.z, b.z), fmaxf(a.w, b.w));
}

__global__ __launch_bounds__(128)
void pool_kernel(const float4* __restrict__ feats4, float4* __restrict__ out4)
{
    const int warp = threadIdx.x >> 5;
    const int lane = threadIdx.x & 31;
    const int cell = blockIdx.x * 4 + warp;

    const int off = g_offset[cell];
    const int cnt = g_count[cell];

    float4 m = make_float4(0.f, 0.f, 0.f, 0.f);  // max(.,0) + empty cells

    for (int base = 0; base < cnt; base += 32) {
        const int chunk = min(32, cnt - base);
        int idx = g_pidx[off + base + min(lane, chunk - 1)];

        for (int i = 0; i < chunk; i += 8) {
            int j0 = __shfl_sync(0xffffffffu, idx, i);
            int j1 = __shfl_sync(0xffffffffu, idx, min(i + 1, chunk - 1));
            int j2 = __shfl_sync(0xffffffffu, idx, min(i + 2, chunk - 1));
            int j3 = __shfl_sync(0xffffffffu, idx, min(i + 3, chunk - 1));
            int j4 = __shfl_sync(0xffffffffu, idx, min(i + 4, chunk - 1));
            int j5 = __shfl_sync(0xffffffffu, idx, min(i + 5, chunk - 1));
            int j6 = __shfl_sync(0xffffffffu, idx, min(i + 6, chunk - 1));
            int j7 = __shfl_sync(0xffffffffu, idx, min(i + 7, chunk - 1));
            float4 a = feats4[(size_t)j0 * (FEAT / 4) + lane];
            float4 b = feats4[(size_t)j1 * (FEAT / 4) + lane];
            float4 c = feats4[(size_t)j2 * (FEAT / 4) + lane];
            float4 d = feats4[(size_t)j3 * (FEAT / 4) + lane];
            float4 e = feats4[(size_t)j4 * (FEAT / 4) + lane];
            float4 f = feats4[(size_t)j5 * (FEAT / 4) + lane];
            float4 g = feats4[(size_t)j6 * (FEAT / 4) + lane];
            float4 h = feats4[(size_t)j7 * (FEAT / 4) + lane];
            m = max4(m, max4(max4(max4(a, b), max4(c, d)),
                             max4(max4(e, f), max4(g, h))));
        }
    }

    out4[(size_t)cell * (FEAT / 4) + lane] = m;

    if (lane == 0) g_count[cell] = 0;   // restore invariant for next replay
}

extern "C" void kernel_launch(void* const* d_in, const int* in_sizes, int n_in,
                              void* d_out, int out_size)
{
    const float* feats = (const float*)d_in[0];   // [N, 128]
    const float* pts   = (const float*)d_in[1];   // [N, 3]

    const int n = in_sizes[1] / 3;

    const int groups = (n + 3) / 4;
    cell_kernel   <<<(groups + 255) / 256, 256>>>(pts, n);
    scan_kernel   <<<1, 1024>>>();
    scatter_kernel<<<(n + 255) / 256, 256>>>(n);
    pool_kernel   <<<NUM_CELLS / 4, 128>>>(
        reinterpret_cast<const float4*>(feats),
        reinterpret_cast<float4*>(d_out));
}